// round 3
// baseline (speedup 1.0000x reference)
#include <cuda_runtime.h>
#include <cuda_bf16.h>
#include <cstdint>
#include <cstddef>

// Problem constants
#define NB 16
#define NT 1024
#define ND 256
// DS = 4

// Tile config: BM x BN per CTA, 2 CTAs/SM for phase overlap
#define BM 128
#define BN 64
#define LDSX 264   // bf16 elems per smem row (528B = 33*16B, odd 16B stride -> conflict-free ldmatrix)
#define SMEM_BYTES ((BM + BN) * LDSX * 2)   // ~101 KB

#define NTILE_S (NT / BN)   // 16
#define NTILE_T (NT / BM)   // 8
#define NPART (NB * NTILE_T * NTILE_S)  // 2048

// Scratch (no allocations allowed -> __device__ globals)
__device__ __align__(16) __nv_bfloat16 g_zbf[NB * NT * ND];  // 8.4 MB
__device__ float  g_z2[NB * NT];
__device__ double g_partial[NPART];

// ---------------------------------------------------------------------------
// Kernel 0: z -> bf16 copy + per-row sum of squares (z2)
// Each warp handles 2 rows (4 independent float4 streams -> better MLP).
// grid = NB*NT/16 blocks of 256 threads.
// ---------------------------------------------------------------------------
__global__ void prep_kernel(const float* __restrict__ z) {
    const int warp = blockIdx.x * 8 + (threadIdx.x >> 5);
    const int lane = threadIdx.x & 31;
    const int row0 = warp * 2;

    const float4* zr0 = reinterpret_cast<const float4*>(z) + (size_t)row0 * (ND / 4);
    const float4* zr1 = zr0 + (ND / 4);
    float4 a0 = zr0[lane];
    float4 a1 = zr0[lane + 32];
    float4 b0 = zr1[lane];
    float4 b1 = zr1[lane + 32];

    float s0 = a0.x*a0.x + a0.y*a0.y + a0.z*a0.z + a0.w*a0.w
             + a1.x*a1.x + a1.y*a1.y + a1.z*a1.z + a1.w*a1.w;
    float s1 = b0.x*b0.x + b0.y*b0.y + b0.z*b0.z + b0.w*b0.w
             + b1.x*b1.x + b1.y*b1.y + b1.z*b1.z + b1.w*b1.w;
    #pragma unroll
    for (int o = 16; o; o >>= 1) {
        s0 += __shfl_xor_sync(0xffffffffu, s0, o);
        s1 += __shfl_xor_sync(0xffffffffu, s1, o);
    }
    if (lane == 0) { g_z2[row0] = s0; g_z2[row0 + 1] = s1; }

    // One row of g_zbf = ND bf16 = ND*2 bytes = ND/4 uint2 (= 64).
    uint2* d0 = reinterpret_cast<uint2*>(g_zbf + (size_t)row0 * ND);
    uint2* d1 = d0 + (ND / 4);   // FIX: was ND/2 (skipped a row, left odd rows zero)
    auto pack = [](float4 v) {
        __nv_bfloat162 lo = __floats2bfloat162_rn(v.x, v.y);
        __nv_bfloat162 hi = __floats2bfloat162_rn(v.z, v.w);
        uint2 p;
        p.x = *reinterpret_cast<uint32_t*>(&lo);
        p.y = *reinterpret_cast<uint32_t*>(&hi);
        return p;
    };
    d0[lane]      = pack(a0);
    d0[lane + 32] = pack(a1);
    d1[lane]      = pack(b0);
    d1[lane + 32] = pack(b1);
}

// ---------------------------------------------------------------------------
// Main fused kernel (per (b, t-tile(128), s-tile(64))):
//   Phase A: G = Zt * Zs^T  (128x64x256 bf16 mma.sync m16n8k16)
//   Phase B: stream gt_dT tile, w = expf(sum g^2/(2 sigma^2)),
//            partial += w * (z2[t] - G[t,s])
// 2 CTAs/SM -> one CTA's GEMM overlaps the other's DRAM stream.
// ---------------------------------------------------------------------------
#define LDSM4(r0, r1, r2, r3, addr)                                              \
    asm volatile("ldmatrix.sync.aligned.m8n8.x4.shared.b16 {%0,%1,%2,%3}, [%4];" \
                 : "=r"(r0), "=r"(r1), "=r"(r2), "=r"(r3) : "r"(addr))

#define MMA16816(d, a, b0r, b1r)                                                 \
    asm volatile("mma.sync.aligned.m16n8k16.row.col.f32.bf16.bf16.f32 "          \
                 "{%0,%1,%2,%3}, {%4,%5,%6,%7}, {%8,%9}, {%0,%1,%2,%3};"         \
                 : "+f"(d[0]), "+f"(d[1]), "+f"(d[2]), "+f"(d[3])                \
                 : "r"(a[0]), "r"(a[1]), "r"(a[2]), "r"(a[3]), "r"(b0r), "r"(b1r))

__global__ void __launch_bounds__(256, 2)
main_kernel(const float* __restrict__ gt, const float* __restrict__ sigma) {
    extern __shared__ __align__(16) __nv_bfloat16 sm[];
    __nv_bfloat16* As = sm;                 // 128 rows (Zt)
    __nv_bfloat16* Bs = sm + BM * LDSX;     //  64 rows (Zs)

    const int bb = blockIdx.z;
    const int t0 = blockIdx.y * BM;
    const int sB = blockIdx.x * BN;
    const int tid = threadIdx.x;

    // ---- load Zt (128 rows) / Zs (64 rows) tiles into smem ----
    {
        const int4* gzt = reinterpret_cast<const int4*>(g_zbf + ((size_t)bb * NT + t0) * ND);
        const int4* gzs = reinterpret_cast<const int4*>(g_zbf + ((size_t)bb * NT + sB) * ND);
        #pragma unroll
        for (int i = 0; i < 16; i++) {
            int idx = tid + i * 256;           // 0..4095 : 128 rows x 32 int4
            int r = idx >> 5, c = idx & 31;
            *reinterpret_cast<int4*>(As + r * LDSX + c * 8) = gzt[idx];
        }
        #pragma unroll
        for (int i = 0; i < 8; i++) {
            int idx = tid + i * 256;           // 0..2047 : 64 rows x 32 int4
            int r = idx >> 5, c = idx & 31;
            *reinterpret_cast<int4*>(Bs + r * LDSX + c * 8) = gzs[idx];
        }
    }
    __syncthreads();

    const int lane = tid & 31;
    const int wid  = tid >> 5;
    const int wm = (wid & 3) * 32;   // warp rows: 0,32,64,96
    const int wn = (wid >> 2) * 32;  // warp cols: 0,32

    float acc[2][4][4];
    #pragma unroll
    for (int mi = 0; mi < 2; mi++)
        #pragma unroll
        for (int ni = 0; ni < 4; ni++)
            #pragma unroll
            for (int r = 0; r < 4; r++) acc[mi][ni][r] = 0.f;

    const uint32_t aBase = (uint32_t)__cvta_generic_to_shared(As);
    const uint32_t bBase = (uint32_t)__cvta_generic_to_shared(Bs);

    const uint32_t aAddr0 = aBase + (((wm + (lane & 15)) * LDSX + (lane >> 4) * 8)) * 2;
    const uint32_t bAddr0 = bBase + (((wn + (lane & 7) + ((lane >> 4) << 3)) * LDSX
                                     + ((lane >> 3) & 1) * 8)) * 2;

    #pragma unroll
    for (int kk = 0; kk < 16; kk++) {
        uint32_t a[2][4];
        #pragma unroll
        for (int mi = 0; mi < 2; mi++) {
            uint32_t addr = aAddr0 + (uint32_t)(mi * 16 * LDSX * 2) + (uint32_t)(kk * 32);
            LDSM4(a[mi][0], a[mi][1], a[mi][2], a[mi][3], addr);
        }
        uint32_t bf[4][2];
        #pragma unroll
        for (int nj = 0; nj < 2; nj++) {
            uint32_t addr = bAddr0 + (uint32_t)(nj * 16 * LDSX * 2) + (uint32_t)(kk * 32);
            uint32_t r0, r1, r2, r3;
            LDSM4(r0, r1, r2, r3, addr);
            bf[2 * nj][0] = r0;     bf[2 * nj][1] = r1;
            bf[2 * nj + 1][0] = r2; bf[2 * nj + 1][1] = r3;
        }
        #pragma unroll
        for (int mi = 0; mi < 2; mi++)
            #pragma unroll
            for (int ni = 0; ni < 4; ni++)
                MMA16816(acc[mi][ni], a[mi], bf[ni][0], bf[ni][1]);
    }

    // ---- Phase B: stream gt, fuse w + reduction ----
    float sg0 = sigma[0], sg1 = sigma[1], sg2 = sigma[2], sg3 = sigma[3];
    const float inv0 = 1.0f / (2.0f * sg0 * sg0);
    const float inv1 = 1.0f / (2.0f * sg1 * sg1);
    const float inv2 = 1.0f / (2.0f * sg2 * sg2);
    const float inv3 = 1.0f / (2.0f * sg3 * sg3);

    const int rowc = lane >> 2;          // 0..7
    const int colc = (lane & 3) * 2;     // 0,2,4,6

    float z2v[2][2];
    #pragma unroll
    for (int mi = 0; mi < 2; mi++)
        #pragma unroll
        for (int h = 0; h < 2; h++)
            z2v[mi][h] = g_z2[bb * NT + t0 + wm + mi * 16 + rowc + h * 8];

    float part = 0.f;
    #pragma unroll
    for (int mi = 0; mi < 2; mi++) {
        #pragma unroll
        for (int h = 0; h < 2; h++) {
            const int t = t0 + wm + mi * 16 + rowc + h * 8;
            // gt float4 index for (b,t,s) is (b*NT+t)*NT + s
            const float4* gp = reinterpret_cast<const float4*>(gt)
                             + ((size_t)bb * NT + t) * NT + (sB + wn + colc);
            const float zz = z2v[mi][h];
            #pragma unroll
            for (int ni = 0; ni < 4; ni++) {
                float4 gA = __ldcs(gp + ni * 8);      // (t, s)
                float4 gB = __ldcs(gp + ni * 8 + 1);  // (t, s+1)
                float q0 = gA.x * gA.x * inv0 + gA.y * gA.y * inv1
                         + gA.z * gA.z * inv2 + gA.w * gA.w * inv3;
                float q1 = gB.x * gB.x * inv0 + gB.y * gB.y * inv1
                         + gB.z * gB.z * inv2 + gB.w * gB.w * inv3;
                float w0 = __expf(q0);
                float w1 = __expf(q1);
                part += w0 * (zz - acc[mi][ni][h * 2 + 0]);
                part += w1 * (zz - acc[mi][ni][h * 2 + 1]);
            }
        }
    }

    // ---- CTA reduction (deterministic), one partial per CTA ----
    #pragma unroll
    for (int o = 16; o; o >>= 1) part += __shfl_xor_sync(0xffffffffu, part, o);
    __syncthreads();  // tiles no longer needed
    double* red = reinterpret_cast<double*>(sm);
    if (lane == 0) red[wid] = (double)part;
    __syncthreads();
    if (tid == 0) {
        double ssum = 0.0;
        #pragma unroll
        for (int i = 0; i < 8; i++) ssum += red[i];
        g_partial[(blockIdx.z * NTILE_T + blockIdx.y) * NTILE_S + blockIdx.x] = ssum;
    }
}

// ---------------------------------------------------------------------------
// Finalize: fixed-order tree reduction of partials -> scalar loss
// ---------------------------------------------------------------------------
__global__ void finalize_kernel(float* __restrict__ out) {
    __shared__ double red[256];
    double v = 0.0;
    for (int i = threadIdx.x; i < NPART; i += 256) v += g_partial[i];
    red[threadIdx.x] = v;
    __syncthreads();
    for (int off = 128; off; off >>= 1) {
        if (threadIdx.x < off) red[threadIdx.x] += red[threadIdx.x + off];
        __syncthreads();
    }
    if (threadIdx.x == 0)
        out[0] = (float)(red[0] * (2.0 / ((double)NB * (double)NT * (double)NT)));
}

// ---------------------------------------------------------------------------
extern "C" void kernel_launch(void* const* d_in, const int* in_sizes, int n_in,
                              void* d_out, int out_size) {
    const float* z     = (const float*)d_in[0];  // [16,1024,256]
    const float* gt    = (const float*)d_in[1];  // [16,1024,1024,4]
    const float* sigma = (const float*)d_in[2];  // [4]
    float* out = (float*)d_out;

    cudaFuncSetAttribute(main_kernel, cudaFuncAttributeMaxDynamicSharedMemorySize, SMEM_BYTES);

    prep_kernel<<<NB * NT / 16, 256>>>(z);
    main_kernel<<<dim3(NTILE_S, NTILE_T, NB), 256, SMEM_BYTES>>>(gt, sigma);
    finalize_kernel<<<1, 256>>>(out);
}